// round 3
// baseline (speedup 1.0000x reference)
#include <cuda_runtime.h>
#include <cuda_bf16.h>

// ---------------------------------------------------------------------------
// UFF energy: e_bond + e_angle + e_torsion + e_inversion + e_vdw  -> out[B]
// B=8, N=50000 per the reference. Coords are repacked to float4 (16B aligned)
// so every random gather is a single LDG.128 hitting one 32B L2 sector.
// ---------------------------------------------------------------------------

#define NBATCH 8
#define MAX_ATOMS 50000

// scratch: padded coords, 8*50000*16B = 6.4 MB
__device__ float4 g_coords[NBATCH * MAX_ATOMS];

__device__ __forceinline__ float clip1(float x) {
    return fminf(fmaxf(x, -0.999999f), 0.999999f);
}

// warp -> shared -> global reduction of 8 per-batch partial sums
__device__ __forceinline__ void block_reduce_add(float acc[NBATCH], float* __restrict__ out) {
    #pragma unroll
    for (int b = 0; b < NBATCH; b++) {
        #pragma unroll
        for (int off = 16; off > 0; off >>= 1)
            acc[b] += __shfl_down_sync(0xFFFFFFFFu, acc[b], off);
    }
    __shared__ float s[NBATCH];
    if (threadIdx.x < NBATCH) s[threadIdx.x] = 0.0f;
    __syncthreads();
    if ((threadIdx.x & 31) == 0) {
        #pragma unroll
        for (int b = 0; b < NBATCH; b++) atomicAdd(&s[b], acc[b]);
    }
    __syncthreads();
    if (threadIdx.x < NBATCH) atomicAdd(&out[threadIdx.x], s[threadIdx.x]);
}

// ---------------------------------------------------------------------------
// pack coords (B,N,3) f32 -> float4, and zero the output
// ---------------------------------------------------------------------------
__global__ void pack_kernel(const float* __restrict__ coords, float* __restrict__ out,
                            int total) {
    int i = blockIdx.x * blockDim.x + threadIdx.x;
    if (i < NBATCH) out[i] = 0.0f;
    if (i < total) {
        float x = coords[3 * i + 0];
        float y = coords[3 * i + 1];
        float z = coords[3 * i + 2];
        g_coords[i] = make_float4(x, y, z, 0.0f);
    }
}

// ---------------------------------------------------------------------------
// bond stretch: 0.5 * k * (|r_ij| - r0)^2
// ---------------------------------------------------------------------------
__global__ __launch_bounds__(256)
void bond_kernel(const int2* __restrict__ idx,
                 const float* __restrict__ rest,
                 const float* __restrict__ kf,
                 float* __restrict__ out, int n, int natoms) {
    float acc[NBATCH];
    #pragma unroll
    for (int b = 0; b < NBATCH; b++) acc[b] = 0.0f;

    for (int i = blockIdx.x * blockDim.x + threadIdx.x; i < n;
         i += gridDim.x * blockDim.x) {
        int2 p = __ldg(&idx[i]);
        float r0 = __ldg(&rest[i]);
        float k2 = 0.5f * __ldg(&kf[i]);
        #pragma unroll
        for (int b = 0; b < NBATCH; b++) {
            const float4 a = __ldg(&g_coords[b * natoms + p.x]);
            const float4 c = __ldg(&g_coords[b * natoms + p.y]);
            float dx = a.x - c.x, dy = a.y - c.y, dz = a.z - c.z;
            float dist = sqrtf(fmaf(dx, dx, fmaf(dy, dy, dz * dz)));
            float dd = dist - r0;
            acc[b] += k2 * dd * dd;
        }
    }
    block_reduce_add(acc, out);
}

// ---------------------------------------------------------------------------
// angle bend: K * (c0 + c1*ct + c2*(cs - ss))
// ---------------------------------------------------------------------------
__global__ __launch_bounds__(256)
void angle_kernel(const int* __restrict__ idx,
                  const float* __restrict__ kf,
                  const float* __restrict__ c0,
                  const float* __restrict__ c1,
                  const float* __restrict__ c2,
                  float* __restrict__ out, int n, int natoms) {
    float acc[NBATCH];
    #pragma unroll
    for (int b = 0; b < NBATCH; b++) acc[b] = 0.0f;

    for (int i = blockIdx.x * blockDim.x + threadIdx.x; i < n;
         i += gridDim.x * blockDim.x) {
        int i0 = __ldg(&idx[3 * i + 0]);
        int i1 = __ldg(&idx[3 * i + 1]);
        int i2 = __ldg(&idx[3 * i + 2]);
        float K  = __ldg(&kf[i]);
        float a0 = __ldg(&c0[i]);
        float a1 = __ldg(&c1[i]);
        float a2 = __ldg(&c2[i]);
        #pragma unroll
        for (int b = 0; b < NBATCH; b++) {
            int base = b * natoms;
            const float4 p1 = __ldg(&g_coords[base + i0]);
            const float4 p2 = __ldg(&g_coords[base + i1]);
            const float4 p3 = __ldg(&g_coords[base + i2]);
            float v1x = p1.x - p2.x, v1y = p1.y - p2.y, v1z = p1.z - p2.z;
            float v2x = p3.x - p2.x, v2y = p3.y - p2.y, v2z = p3.z - p2.z;
            float dot = fmaf(v1x, v2x, fmaf(v1y, v2y, v1z * v2z));
            float n1 = fmaf(v1x, v1x, fmaf(v1y, v1y, v1z * v1z));
            float n2 = fmaf(v2x, v2x, fmaf(v2y, v2y, v2z * v2z));
            float inv = rsqrtf(fmaxf(n1 * n2, 1e-24f));
            float ct = clip1(dot * inv);
            float cs = ct * ct;
            float ss = fmaxf(1.0f - cs, 1e-12f);
            acc[b] += K * fmaf(a2, cs - ss, fmaf(a1, ct, a0));
        }
    }
    block_reduce_add(acc, out);
}

// ---------------------------------------------------------------------------
// torsion: 0.5 * V * (1 - cos_term * cos(n*phi)); cos(n*phi) = T_n(cos phi)
// ---------------------------------------------------------------------------
__global__ __launch_bounds__(256)
void torsion_kernel(const int4* __restrict__ idx,
                    const float* __restrict__ kf,
                    const int* __restrict__ order,
                    const float* __restrict__ costerm,
                    float* __restrict__ out, int n, int natoms) {
    float acc[NBATCH];
    #pragma unroll
    for (int b = 0; b < NBATCH; b++) acc[b] = 0.0f;

    for (int i = blockIdx.x * blockDim.x + threadIdx.x; i < n;
         i += gridDim.x * blockDim.x) {
        int4 q = __ldg(&idx[i]);
        float V2 = 0.5f * __ldg(&kf[i]);
        int   ord = __ldg(&order[i]);
        float ctm = __ldg(&costerm[i]);
        #pragma unroll
        for (int b = 0; b < NBATCH; b++) {
            int base = b * natoms;
            const float4 q1 = __ldg(&g_coords[base + q.x]);
            const float4 q2 = __ldg(&g_coords[base + q.y]);
            const float4 q3 = __ldg(&g_coords[base + q.z]);
            const float4 q4 = __ldg(&g_coords[base + q.w]);
            float b1x = q2.x - q1.x, b1y = q2.y - q1.y, b1z = q2.z - q1.z;
            float b2x = q3.x - q2.x, b2y = q3.y - q2.y, b2z = q3.z - q2.z;
            float b3x = q4.x - q3.x, b3y = q4.y - q3.y, b3z = q4.z - q3.z;
            // n1 = b1 x b2, n2 = b2 x b3
            float n1x = b1y * b2z - b1z * b2y;
            float n1y = b1z * b2x - b1x * b2z;
            float n1z = b1x * b2y - b1y * b2x;
            float n2x = b2y * b3z - b2z * b3y;
            float n2y = b2z * b3x - b2x * b3z;
            float n2z = b2x * b3y - b2y * b3x;
            float dot = fmaf(n1x, n2x, fmaf(n1y, n2y, n1z * n2z));
            float m1 = fmaf(n1x, n1x, fmaf(n1y, n1y, n1z * n1z));
            float m2 = fmaf(n2x, n2x, fmaf(n2y, n2y, n2z * n2z));
            float c = clip1(dot * rsqrtf(fmaxf(m1 * m2, 1e-24f)));
            // cos(ord * phi) via Chebyshev: T_k(c), ord in [1,6]
            float t0 = 1.0f, t1 = c;
            for (int k = 1; k < ord; k++) {
                float t2 = fmaf(2.0f * c, t1, -t0);
                t0 = t1;
                t1 = t2;
            }
            acc[b] += V2 * (1.0f - ctm * t1);
        }
    }
    block_reduce_add(acc, out);
}

// ---------------------------------------------------------------------------
// inversion (Wilson angle): K * (c0 + c1*sinY + c2*(2*sinY^2 - 1))
// ---------------------------------------------------------------------------
__global__ __launch_bounds__(256)
void inversion_kernel(const int4* __restrict__ idx,
                      const float* __restrict__ kf,
                      const float* __restrict__ c0,
                      const float* __restrict__ c1,
                      const float* __restrict__ c2,
                      float* __restrict__ out, int n, int natoms) {
    float acc[NBATCH];
    #pragma unroll
    for (int b = 0; b < NBATCH; b++) acc[b] = 0.0f;

    for (int i = blockIdx.x * blockDim.x + threadIdx.x; i < n;
         i += gridDim.x * blockDim.x) {
        int4 q = __ldg(&idx[i]);
        float K  = __ldg(&kf[i]);
        float a0 = __ldg(&c0[i]);
        float a1 = __ldg(&c1[i]);
        float a2 = __ldg(&c2[i]);
        #pragma unroll
        for (int b = 0; b < NBATCH; b++) {
            int base = b * natoms;
            const float4 pi = __ldg(&g_coords[base + q.x]);
            const float4 pj = __ldg(&g_coords[base + q.y]);  // central
            const float4 pk = __ldg(&g_coords[base + q.z]);
            const float4 pl = __ldg(&g_coords[base + q.w]);
            float ix = pi.x - pj.x, iy = pi.y - pj.y, iz = pi.z - pj.z;
            float kx = pk.x - pj.x, ky = pk.y - pj.y, kz = pk.z - pj.z;
            float lx = pl.x - pj.x, ly = pl.y - pj.y, lz = pl.z - pj.z;
            // nrm = rji x rjk
            float nx = iy * kz - iz * ky;
            float ny = iz * kx - ix * kz;
            float nz = ix * ky - iy * kx;
            float dot = fmaf(nx, lx, fmaf(ny, ly, nz * lz));
            float m1 = fmaf(nx, nx, fmaf(ny, ny, nz * nz));
            float m2 = fmaf(lx, lx, fmaf(ly, ly, lz * lz));
            float cosY = clip1(dot * rsqrtf(fmaxf(m1 * m2, 1e-24f)));
            float sinY = sqrtf(fmaxf(1.0f - cosY * cosY, 0.0f));
            acc[b] += K * fmaf(a2, fmaf(2.0f * sinY, sinY, -1.0f), fmaf(a1, sinY, a0));
        }
    }
    block_reduce_add(acc, out);
}

// ---------------------------------------------------------------------------
// vdW LJ: D * ((R/r)^12 - 2 (R/r)^6) if d2 <= threshold_sq
// ---------------------------------------------------------------------------
__global__ __launch_bounds__(256)
void vdw_kernel(const int2* __restrict__ idx,
                const float* __restrict__ rmin,
                const float* __restrict__ depth,
                const float* __restrict__ thr,
                float* __restrict__ out, int n, int natoms) {
    float acc[NBATCH];
    #pragma unroll
    for (int b = 0; b < NBATCH; b++) acc[b] = 0.0f;

    for (int i = blockIdx.x * blockDim.x + threadIdx.x; i < n;
         i += gridDim.x * blockDim.x) {
        int2 p = __ldg(&idx[i]);
        float R  = __ldg(&rmin[i]);
        float D  = __ldg(&depth[i]);
        float t2 = __ldg(&thr[i]);
        float R2 = R * R;
        #pragma unroll
        for (int b = 0; b < NBATCH; b++) {
            int base = b * natoms;
            const float4 a = __ldg(&g_coords[base + p.x]);
            const float4 c = __ldg(&g_coords[base + p.y]);
            float dx = a.x - c.x, dy = a.y - c.y, dz = a.z - c.z;
            float d2 = fmaf(dx, dx, fmaf(dy, dy, dz * dz));
            float x2 = R2 / fmaxf(d2, 1e-12f);
            float x6 = x2 * x2 * x2;
            float e = D * (fmaf(x6, x6, -2.0f * x6));
            acc[b] += (d2 <= t2) ? e : 0.0f;
        }
    }
    block_reduce_add(acc, out);
}

// ---------------------------------------------------------------------------
// launch
// ---------------------------------------------------------------------------
extern "C" void kernel_launch(void* const* d_in, const int* in_sizes, int n_in,
                              void* d_out, int out_size) {
    const float* coords      = (const float*)d_in[0];
    const int*   bond_index  = (const int*)d_in[1];
    const float* bond_r0     = (const float*)d_in[2];
    const float* bond_k      = (const float*)d_in[3];
    const int*   angle_index = (const int*)d_in[4];
    const float* angle_k     = (const float*)d_in[5];
    const float* angle_c0    = (const float*)d_in[6];
    const float* angle_c1    = (const float*)d_in[7];
    const float* angle_c2    = (const float*)d_in[8];
    const int*   tor_index   = (const int*)d_in[9];
    const float* tor_k       = (const float*)d_in[10];
    const int*   tor_order   = (const int*)d_in[11];
    const float* tor_cos     = (const float*)d_in[12];
    const int*   inv_index   = (const int*)d_in[13];
    const float* inv_k       = (const float*)d_in[14];
    const float* inv_c0      = (const float*)d_in[15];
    const float* inv_c1      = (const float*)d_in[16];
    const float* inv_c2      = (const float*)d_in[17];
    const int*   nb_index    = (const int*)d_in[18];
    const float* vdw_min     = (const float*)d_in[19];
    const float* vdw_depth   = (const float*)d_in[20];
    const float* vdw_thr     = (const float*)d_in[21];
    float* out = (float*)d_out;

    const int NB = in_sizes[1]  / 2;
    const int NA = in_sizes[4]  / 3;
    const int NT = in_sizes[9]  / 4;
    const int NI = in_sizes[13] / 4;
    const int NC = in_sizes[18] / 2;
    const int natoms = in_sizes[0] / (3 * NBATCH);   // B fixed = 8
    const int total  = NBATCH * natoms;

    const int T = 256;
    pack_kernel<<<(total + T - 1) / T, T>>>(coords, out, total);
    bond_kernel<<<(NB + T - 1) / T, T>>>((const int2*)bond_index, bond_r0, bond_k,
                                         out, NB, natoms);
    angle_kernel<<<(NA + T - 1) / T, T>>>(angle_index, angle_k, angle_c0, angle_c1,
                                          angle_c2, out, NA, natoms);
    torsion_kernel<<<(NT + T - 1) / T, T>>>((const int4*)tor_index, tor_k, tor_order,
                                            tor_cos, out, NT, natoms);
    inversion_kernel<<<(NI + T - 1) / T, T>>>((const int4*)inv_index, inv_k, inv_c0,
                                              inv_c1, inv_c2, out, NI, natoms);
    vdw_kernel<<<(NC + T - 1) / T, T>>>((const int2*)nb_index, vdw_min, vdw_depth,
                                        vdw_thr, out, NC, natoms);
}

// round 4
// speedup vs baseline: 3.0937x; 3.0937x over previous
#include <cuda_runtime.h>
#include <cuda_bf16.h>

// ---------------------------------------------------------------------------
// UFF energy -> out[8]. Batch-major coords: g_coords[atom*8 + b] so the 8
// batch gathers of one atom are a single 128B-aligned cache line, and 8
// consecutive lanes (handling the 8 batches of one term) read it as ONE
// coalesced 128B transaction. All 5 term types fused into one kernel.
// ---------------------------------------------------------------------------

#define NBATCH 8
#define MAX_ATOMS 50000

// [atom][batch] float4, 50000*8*16B = 6.4 MB, 128B-aligned per atom
__device__ float4 g_coords[MAX_ATOMS * NBATCH];

__device__ __forceinline__ float clip1(float x) {
    return fminf(fmaxf(x, -0.999999f), 0.999999f);
}

// ---------------------------------------------------------------------------
// pack coords (B,N,3) f32 -> batch-major float4; also zero the output
// ---------------------------------------------------------------------------
__global__ void pack_kernel(const float* __restrict__ coords,
                            float* __restrict__ out, int natoms) {
    int i = blockIdx.x * blockDim.x + threadIdx.x;
    if (i < NBATCH) out[i] = 0.0f;
    if (i < natoms * NBATCH) {
        int atom = i >> 3;
        int b    = i & 7;
        size_t src = ((size_t)b * natoms + atom) * 3;
        g_coords[i] = make_float4(coords[src], coords[src + 1], coords[src + 2], 0.0f);
    }
}

// ---------------------------------------------------------------------------
// per-block reduction: each thread holds energy for its (term, batch=lane&7).
// shfl folds terms with the same batch lane; shared folds warps; one global
// atomic per batch per block.
// ---------------------------------------------------------------------------
__device__ __forceinline__ void reduce_out(float e, float* __restrict__ out) {
    e += __shfl_down_sync(0xFFFFFFFFu, e, 16);
    e += __shfl_down_sync(0xFFFFFFFFu, e, 8);
    __shared__ float s[NBATCH];
    if (threadIdx.x < NBATCH) s[threadIdx.x] = 0.0f;
    __syncthreads();
    if ((threadIdx.x & 31) < NBATCH) atomicAdd(&s[threadIdx.x & 7], e);
    __syncthreads();
    if (threadIdx.x < NBATCH) atomicAdd(&out[threadIdx.x], s[threadIdx.x]);
}

// ---------------------------------------------------------------------------
// fused term kernel. Block ranges (in order): vdw | torsion | angle | bond |
// inversion. 256 threads = 32 term-groups x 8 batches. Grid-stride per type.
// ---------------------------------------------------------------------------
__global__ __launch_bounds__(256)
void fused_kernel(
    // vdw
    const int2* __restrict__ cidx, const float* __restrict__ cR,
    const float* __restrict__ cD,  const float* __restrict__ cT,
    int nc, int cBlocks,
    // torsion
    const int4* __restrict__ tidx, const float* __restrict__ tk,
    const int* __restrict__ tord,  const float* __restrict__ tcos,
    int nt, int tBlocks,
    // angle
    const int* __restrict__ aidx,  const float* __restrict__ ak,
    const float* __restrict__ ac0, const float* __restrict__ ac1,
    const float* __restrict__ ac2, int na, int aBlocks,
    // bond
    const int2* __restrict__ bidx, const float* __restrict__ br0,
    const float* __restrict__ bk,  int nb, int bBlocks,
    // inversion
    const int4* __restrict__ iidx, const float* __restrict__ ik,
    const float* __restrict__ ic0, const float* __restrict__ ic1,
    const float* __restrict__ ic2, int ni, int iBlocks,
    float* __restrict__ out)
{
    const int blk = blockIdx.x;
    const int b   = threadIdx.x & 7;   // batch
    const int grp = threadIdx.x >> 3;  // term-group within block (0..31)
    float e = 0.0f;

    if (blk < cBlocks) {
        // ---------------- vdW LJ ----------------
        const int stride = cBlocks * 32;
        for (int t = blk * 32 + grp; t < nc; t += stride) {
            int2  p  = __ldg(&cidx[t]);
            float R  = __ldg(&cR[t]);
            float D  = __ldg(&cD[t]);
            float t2 = __ldg(&cT[t]);
            const float4 A = __ldg(&g_coords[p.x * NBATCH + b]);
            const float4 C = __ldg(&g_coords[p.y * NBATCH + b]);
            float dx = A.x - C.x, dy = A.y - C.y, dz = A.z - C.z;
            float d2 = fmaf(dx, dx, fmaf(dy, dy, dz * dz));
            float x2 = (R * R) * __frcp_rn(fmaxf(d2, 1e-12f));
            float x6 = x2 * x2 * x2;
            float ep = D * fmaf(x6, x6, -2.0f * x6);
            e += (d2 <= t2) ? ep : 0.0f;
        }
    } else if (blk < cBlocks + tBlocks) {
        // ---------------- torsion ----------------
        const int base = cBlocks, stride = tBlocks * 32;
        for (int t = (blk - base) * 32 + grp; t < nt; t += stride) {
            int4  q   = __ldg(&tidx[t]);
            float V2  = 0.5f * __ldg(&tk[t]);
            int   ord = __ldg(&tord[t]);
            float ctm = __ldg(&tcos[t]);
            const float4 q1 = __ldg(&g_coords[q.x * NBATCH + b]);
            const float4 q2 = __ldg(&g_coords[q.y * NBATCH + b]);
            const float4 q3 = __ldg(&g_coords[q.z * NBATCH + b]);
            const float4 q4 = __ldg(&g_coords[q.w * NBATCH + b]);
            float b1x = q2.x - q1.x, b1y = q2.y - q1.y, b1z = q2.z - q1.z;
            float b2x = q3.x - q2.x, b2y = q3.y - q2.y, b2z = q3.z - q2.z;
            float b3x = q4.x - q3.x, b3y = q4.y - q3.y, b3z = q4.z - q3.z;
            float n1x = b1y * b2z - b1z * b2y;
            float n1y = b1z * b2x - b1x * b2z;
            float n1z = b1x * b2y - b1y * b2x;
            float n2x = b2y * b3z - b2z * b3y;
            float n2y = b2z * b3x - b2x * b3z;
            float n2z = b2x * b3y - b2y * b3x;
            float dot = fmaf(n1x, n2x, fmaf(n1y, n2y, n1z * n2z));
            float m1  = fmaf(n1x, n1x, fmaf(n1y, n1y, n1z * n1z));
            float m2  = fmaf(n2x, n2x, fmaf(n2y, n2y, n2z * n2z));
            float c   = clip1(dot * rsqrtf(fmaxf(m1 * m2, 1e-24f)));
            // cos(ord*phi) = T_ord(cos phi), ord in [1,6]
            float t0 = 1.0f, t1 = c;
            for (int k = 1; k < ord; k++) {
                float tn = fmaf(2.0f * c, t1, -t0);
                t0 = t1; t1 = tn;
            }
            e += V2 * (1.0f - ctm * t1);
        }
    } else if (blk < cBlocks + tBlocks + aBlocks) {
        // ---------------- angle ----------------
        const int base = cBlocks + tBlocks, stride = aBlocks * 32;
        for (int t = (blk - base) * 32 + grp; t < na; t += stride) {
            int i0 = __ldg(&aidx[3 * t + 0]);
            int i1 = __ldg(&aidx[3 * t + 1]);
            int i2 = __ldg(&aidx[3 * t + 2]);
            float K  = __ldg(&ak[t]);
            float a0 = __ldg(&ac0[t]);
            float a1 = __ldg(&ac1[t]);
            float a2 = __ldg(&ac2[t]);
            const float4 p1 = __ldg(&g_coords[i0 * NBATCH + b]);
            const float4 p2 = __ldg(&g_coords[i1 * NBATCH + b]);
            const float4 p3 = __ldg(&g_coords[i2 * NBATCH + b]);
            float v1x = p1.x - p2.x, v1y = p1.y - p2.y, v1z = p1.z - p2.z;
            float v2x = p3.x - p2.x, v2y = p3.y - p2.y, v2z = p3.z - p2.z;
            float dot = fmaf(v1x, v2x, fmaf(v1y, v2y, v1z * v2z));
            float n1  = fmaf(v1x, v1x, fmaf(v1y, v1y, v1z * v1z));
            float n2  = fmaf(v2x, v2x, fmaf(v2y, v2y, v2z * v2z));
            float ct  = clip1(dot * rsqrtf(fmaxf(n1 * n2, 1e-24f)));
            float cs  = ct * ct;
            float ss  = fmaxf(1.0f - cs, 1e-12f);
            e += K * fmaf(a2, cs - ss, fmaf(a1, ct, a0));
        }
    } else if (blk < cBlocks + tBlocks + aBlocks + bBlocks) {
        // ---------------- bond ----------------
        const int base = cBlocks + tBlocks + aBlocks, stride = bBlocks * 32;
        for (int t = (blk - base) * 32 + grp; t < nb; t += stride) {
            int2  p  = __ldg(&bidx[t]);
            float r0 = __ldg(&br0[t]);
            float k2 = 0.5f * __ldg(&bk[t]);
            const float4 A = __ldg(&g_coords[p.x * NBATCH + b]);
            const float4 C = __ldg(&g_coords[p.y * NBATCH + b]);
            float dx = A.x - C.x, dy = A.y - C.y, dz = A.z - C.z;
            float dist = sqrtf(fmaf(dx, dx, fmaf(dy, dy, dz * dz)));
            float dd = dist - r0;
            e += k2 * dd * dd;
        }
    } else {
        // ---------------- inversion ----------------
        const int base = cBlocks + tBlocks + aBlocks + bBlocks, stride = iBlocks * 32;
        for (int t = (blk - base) * 32 + grp; t < ni; t += stride) {
            int4  q  = __ldg(&iidx[t]);
            float K  = __ldg(&ik[t]);
            float a0 = __ldg(&ic0[t]);
            float a1 = __ldg(&ic1[t]);
            float a2 = __ldg(&ic2[t]);
            const float4 pi = __ldg(&g_coords[q.x * NBATCH + b]);
            const float4 pj = __ldg(&g_coords[q.y * NBATCH + b]);  // central
            const float4 pk = __ldg(&g_coords[q.z * NBATCH + b]);
            const float4 pl = __ldg(&g_coords[q.w * NBATCH + b]);
            float ix = pi.x - pj.x, iy = pi.y - pj.y, iz = pi.z - pj.z;
            float kx = pk.x - pj.x, ky = pk.y - pj.y, kz = pk.z - pj.z;
            float lx = pl.x - pj.x, ly = pl.y - pj.y, lz = pl.z - pj.z;
            float nx = iy * kz - iz * ky;
            float ny = iz * kx - ix * kz;
            float nz = ix * ky - iy * kx;
            float dot = fmaf(nx, lx, fmaf(ny, ly, nz * lz));
            float m1  = fmaf(nx, nx, fmaf(ny, ny, nz * nz));
            float m2  = fmaf(lx, lx, fmaf(ly, ly, lz * lz));
            float cosY = clip1(dot * rsqrtf(fmaxf(m1 * m2, 1e-24f)));
            float sinY = sqrtf(fmaxf(1.0f - cosY * cosY, 0.0f));
            e += K * fmaf(a2, fmaf(2.0f * sinY, sinY, -1.0f), fmaf(a1, sinY, a0));
        }
    }

    reduce_out(e, out);
}

// ---------------------------------------------------------------------------
// launch
// ---------------------------------------------------------------------------
static inline int blocks_for(int n_terms, int iters) {
    // 32 term-groups per block, `iters` grid-stride passes
    long long groups = ((long long)n_terms + 32LL * iters - 1) / (32LL * iters);
    return groups < 1 ? 1 : (int)groups;
}

extern "C" void kernel_launch(void* const* d_in, const int* in_sizes, int n_in,
                              void* d_out, int out_size) {
    const float* coords      = (const float*)d_in[0];
    const int*   bond_index  = (const int*)d_in[1];
    const float* bond_r0     = (const float*)d_in[2];
    const float* bond_k      = (const float*)d_in[3];
    const int*   angle_index = (const int*)d_in[4];
    const float* angle_k     = (const float*)d_in[5];
    const float* angle_c0    = (const float*)d_in[6];
    const float* angle_c1    = (const float*)d_in[7];
    const float* angle_c2    = (const float*)d_in[8];
    const int*   tor_index   = (const int*)d_in[9];
    const float* tor_k       = (const float*)d_in[10];
    const int*   tor_order   = (const int*)d_in[11];
    const float* tor_cos     = (const float*)d_in[12];
    const int*   inv_index   = (const int*)d_in[13];
    const float* inv_k       = (const float*)d_in[14];
    const float* inv_c0      = (const float*)d_in[15];
    const float* inv_c1      = (const float*)d_in[16];
    const float* inv_c2      = (const float*)d_in[17];
    const int*   nb_index    = (const int*)d_in[18];
    const float* vdw_min     = (const float*)d_in[19];
    const float* vdw_depth   = (const float*)d_in[20];
    const float* vdw_thr     = (const float*)d_in[21];
    float* out = (float*)d_out;

    const int NB = in_sizes[1]  / 2;
    const int NA = in_sizes[4]  / 3;
    const int NT = in_sizes[9]  / 4;
    const int NI = in_sizes[13] / 4;
    const int NC = in_sizes[18] / 2;
    const int natoms = in_sizes[0] / (3 * NBATCH);  // B fixed = 8
    const int total  = NBATCH * natoms;

    const int T = 256;
    pack_kernel<<<(total + T - 1) / T, T>>>(coords, out, natoms);

    // grid-stride iteration depth chosen to cap total blocks (~19k) so the
    // per-block global atomics (8 each) stay non-binding.
    const int cB = blocks_for(NC, 4);
    const int tB = blocks_for(NT, 2);
    const int aB = blocks_for(NA, 2);
    const int bB = blocks_for(NB, 1);
    const int iB = blocks_for(NI, 1);
    const int grid = cB + tB + aB + bB + iB;

    fused_kernel<<<grid, T>>>(
        (const int2*)nb_index, vdw_min, vdw_depth, vdw_thr, NC, cB,
        (const int4*)tor_index, tor_k, tor_order, tor_cos, NT, tB,
        angle_index, angle_k, angle_c0, angle_c1, angle_c2, NA, aB,
        (const int2*)bond_index, bond_r0, bond_k, NB, bB,
        (const int4*)inv_index, inv_k, inv_c0, inv_c1, inv_c2, NI, iB,
        out);
}

// round 5
// speedup vs baseline: 3.4201x; 1.1055x over previous
#include <cuda_runtime.h>
#include <cuda_bf16.h>
#include <cuda_fp16.h>

// ---------------------------------------------------------------------------
// UFF energy -> out[8]. Coords stored batch-major in HALF precision:
// g_h[atom*8 + b] is a half4 (8B), so one atom's 8 batches = 64B = 2 L2
// sectors (vs 4 for float4). 8 consecutive lanes (8 batches of one term)
// read it as one coalesced 64B transaction. Near-collision vdW pairs
// (d2 < 4) fall back to fp32 reads of the original coords (rare), since
// (R/r)^12 there dominates the energy and is fp16-sensitive.
// ---------------------------------------------------------------------------

#define NBATCH 8
#define MAX_ATOMS 50000

// [atom][batch] half4 packed in uint2: 50000*8*8B = 3.2 MB
__device__ uint2 g_h[MAX_ATOMS * NBATCH];

__device__ __forceinline__ float clip1(float x) {
    return fminf(fmaxf(x, -0.999999f), 0.999999f);
}

__device__ __forceinline__ float3 ldco(int atom, int b) {
    uint2 u = __ldg(&g_h[atom * NBATCH + b]);
    __half2 hxy = *reinterpret_cast<__half2*>(&u.x);
    __half2 hz  = *reinterpret_cast<__half2*>(&u.y);
    float2 xy = __half22float2(hxy);
    return make_float3(xy.x, xy.y, __low2float(hz));
}

// ---------------------------------------------------------------------------
// pack coords (B,N,3) f32 -> batch-major half4; also zero the output
// ---------------------------------------------------------------------------
__global__ void pack_kernel(const float* __restrict__ coords,
                            float* __restrict__ out, int natoms) {
    int i = blockIdx.x * blockDim.x + threadIdx.x;
    if (i < NBATCH) out[i] = 0.0f;
    if (i < natoms * NBATCH) {
        int atom = i >> 3;
        int b    = i & 7;
        size_t src = ((size_t)b * natoms + atom) * 3;
        float x = coords[src], y = coords[src + 1], z = coords[src + 2];
        __half2 hxy = __floats2half2_rn(x, y);
        __half2 hz  = __floats2half2_rn(z, 0.0f);
        uint2 u;
        u.x = *reinterpret_cast<unsigned*>(&hxy);
        u.y = *reinterpret_cast<unsigned*>(&hz);
        g_h[i] = u;
    }
}

// ---------------------------------------------------------------------------
// per-block reduction: thread holds energy for (term, batch = lane&7).
// ---------------------------------------------------------------------------
__device__ __forceinline__ void reduce_out(float e, float* __restrict__ out) {
    e += __shfl_down_sync(0xFFFFFFFFu, e, 16);
    e += __shfl_down_sync(0xFFFFFFFFu, e, 8);
    __shared__ float s[NBATCH];
    if (threadIdx.x < NBATCH) s[threadIdx.x] = 0.0f;
    __syncthreads();
    if ((threadIdx.x & 31) < NBATCH) atomicAdd(&s[threadIdx.x & 7], e);
    __syncthreads();
    if (threadIdx.x < NBATCH) atomicAdd(&out[threadIdx.x], s[threadIdx.x]);
}

// ---------------------------------------------------------------------------
// fused term kernel: vdw | torsion | angle | bond | inversion by block range.
// 256 threads = 32 term-groups x 8 batches.
// ---------------------------------------------------------------------------
__global__ __launch_bounds__(256)
void fused_kernel(
    const float* __restrict__ coords,   // original (B,N,3) fp32, for vdw fallback
    // vdw
    const int2* __restrict__ cidx, const float* __restrict__ cR,
    const float* __restrict__ cD,  const float* __restrict__ cT,
    int nc, int cBlocks,
    // torsion
    const int4* __restrict__ tidx, const float* __restrict__ tk,
    const int* __restrict__ tord,  const float* __restrict__ tcos,
    int nt, int tBlocks,
    // angle
    const int* __restrict__ aidx,  const float* __restrict__ ak,
    const float* __restrict__ ac0, const float* __restrict__ ac1,
    const float* __restrict__ ac2, int na, int aBlocks,
    // bond
    const int2* __restrict__ bidx, const float* __restrict__ br0,
    const float* __restrict__ bk,  int nb, int bBlocks,
    // inversion
    const int4* __restrict__ iidx, const float* __restrict__ ik,
    const float* __restrict__ ic0, const float* __restrict__ ic1,
    const float* __restrict__ ic2, int ni, int iBlocks,
    int natoms, float* __restrict__ out)
{
    const int blk = blockIdx.x;
    const int b   = threadIdx.x & 7;   // batch
    const int grp = threadIdx.x >> 3;  // term-group within block (0..31)
    float e = 0.0f;

    if (blk < cBlocks) {
        // ---------------- vdW LJ ----------------
        const int stride = cBlocks * 32;
        #pragma unroll 2
        for (int t = blk * 32 + grp; t < nc; t += stride) {
            int2  p  = __ldg(&cidx[t]);
            float R  = __ldg(&cR[t]);
            float D  = __ldg(&cD[t]);
            float t2 = __ldg(&cT[t]);
            float3 A = ldco(p.x, b);
            float3 C = ldco(p.y, b);
            float dx = A.x - C.x, dy = A.y - C.y, dz = A.z - C.z;
            float d2 = fmaf(dx, dx, fmaf(dy, dy, dz * dz));
            if (d2 < 4.0f) {
                // rare near-collision: fp16 error on (R/r)^12 would be huge;
                // recompute from original fp32 coords.
                size_t sa = ((size_t)b * natoms + p.x) * 3;
                size_t sc = ((size_t)b * natoms + p.y) * 3;
                float fdx = __ldg(&coords[sa])     - __ldg(&coords[sc]);
                float fdy = __ldg(&coords[sa + 1]) - __ldg(&coords[sc + 1]);
                float fdz = __ldg(&coords[sa + 2]) - __ldg(&coords[sc + 2]);
                d2 = fmaf(fdx, fdx, fmaf(fdy, fdy, fdz * fdz));
            }
            float x2 = (R * R) * __frcp_rn(fmaxf(d2, 1e-12f));
            float x6 = x2 * x2 * x2;
            float ep = D * fmaf(x6, x6, -2.0f * x6);
            e += (d2 <= t2) ? ep : 0.0f;
        }
    } else if (blk < cBlocks + tBlocks) {
        // ---------------- torsion ----------------
        const int base = cBlocks, stride = tBlocks * 32;
        for (int t = (blk - base) * 32 + grp; t < nt; t += stride) {
            int4  q   = __ldg(&tidx[t]);
            float V2  = 0.5f * __ldg(&tk[t]);
            int   ord = __ldg(&tord[t]);
            float ctm = __ldg(&tcos[t]);
            float3 q1 = ldco(q.x, b);
            float3 q2 = ldco(q.y, b);
            float3 q3 = ldco(q.z, b);
            float3 q4 = ldco(q.w, b);
            float b1x = q2.x - q1.x, b1y = q2.y - q1.y, b1z = q2.z - q1.z;
            float b2x = q3.x - q2.x, b2y = q3.y - q2.y, b2z = q3.z - q2.z;
            float b3x = q4.x - q3.x, b3y = q4.y - q3.y, b3z = q4.z - q3.z;
            float n1x = b1y * b2z - b1z * b2y;
            float n1y = b1z * b2x - b1x * b2z;
            float n1z = b1x * b2y - b1y * b2x;
            float n2x = b2y * b3z - b2z * b3y;
            float n2y = b2z * b3x - b2x * b3z;
            float n2z = b2x * b3y - b2y * b3x;
            float dot = fmaf(n1x, n2x, fmaf(n1y, n2y, n1z * n2z));
            float m1  = fmaf(n1x, n1x, fmaf(n1y, n1y, n1z * n1z));
            float m2  = fmaf(n2x, n2x, fmaf(n2y, n2y, n2z * n2z));
            float c   = clip1(dot * rsqrtf(fmaxf(m1 * m2, 1e-24f)));
            // cos(ord*phi) = T_ord(cos phi), ord in [1,6]
            float t0 = 1.0f, t1 = c;
            for (int k = 1; k < ord; k++) {
                float tn = fmaf(2.0f * c, t1, -t0);
                t0 = t1; t1 = tn;
            }
            e += V2 * (1.0f - ctm * t1);
        }
    } else if (blk < cBlocks + tBlocks + aBlocks) {
        // ---------------- angle ----------------
        const int base = cBlocks + tBlocks, stride = aBlocks * 32;
        for (int t = (blk - base) * 32 + grp; t < na; t += stride) {
            int i0 = __ldg(&aidx[3 * t + 0]);
            int i1 = __ldg(&aidx[3 * t + 1]);
            int i2 = __ldg(&aidx[3 * t + 2]);
            float K  = __ldg(&ak[t]);
            float a0 = __ldg(&ac0[t]);
            float a1 = __ldg(&ac1[t]);
            float a2 = __ldg(&ac2[t]);
            float3 p1 = ldco(i0, b);
            float3 p2 = ldco(i1, b);
            float3 p3 = ldco(i2, b);
            float v1x = p1.x - p2.x, v1y = p1.y - p2.y, v1z = p1.z - p2.z;
            float v2x = p3.x - p2.x, v2y = p3.y - p2.y, v2z = p3.z - p2.z;
            float dot = fmaf(v1x, v2x, fmaf(v1y, v2y, v1z * v2z));
            float n1  = fmaf(v1x, v1x, fmaf(v1y, v1y, v1z * v1z));
            float n2  = fmaf(v2x, v2x, fmaf(v2y, v2y, v2z * v2z));
            float ct  = clip1(dot * rsqrtf(fmaxf(n1 * n2, 1e-24f)));
            float cs  = ct * ct;
            float ss  = fmaxf(1.0f - cs, 1e-12f);
            e += K * fmaf(a2, cs - ss, fmaf(a1, ct, a0));
        }
    } else if (blk < cBlocks + tBlocks + aBlocks + bBlocks) {
        // ---------------- bond ----------------
        const int base = cBlocks + tBlocks + aBlocks, stride = bBlocks * 32;
        for (int t = (blk - base) * 32 + grp; t < nb; t += stride) {
            int2  p  = __ldg(&bidx[t]);
            float r0 = __ldg(&br0[t]);
            float k2 = 0.5f * __ldg(&bk[t]);
            float3 A = ldco(p.x, b);
            float3 C = ldco(p.y, b);
            float dx = A.x - C.x, dy = A.y - C.y, dz = A.z - C.z;
            float dist = sqrtf(fmaf(dx, dx, fmaf(dy, dy, dz * dz)));
            float dd = dist - r0;
            e += k2 * dd * dd;
        }
    } else {
        // ---------------- inversion ----------------
        const int base = cBlocks + tBlocks + aBlocks + bBlocks, stride = iBlocks * 32;
        for (int t = (blk - base) * 32 + grp; t < ni; t += stride) {
            int4  q  = __ldg(&iidx[t]);
            float K  = __ldg(&ik[t]);
            float a0 = __ldg(&ic0[t]);
            float a1 = __ldg(&ic1[t]);
            float a2 = __ldg(&ic2[t]);
            float3 pi = ldco(q.x, b);
            float3 pj = ldco(q.y, b);  // central
            float3 pk = ldco(q.z, b);
            float3 pl = ldco(q.w, b);
            float ix = pi.x - pj.x, iy = pi.y - pj.y, iz = pi.z - pj.z;
            float kx = pk.x - pj.x, ky = pk.y - pj.y, kz = pk.z - pj.z;
            float lx = pl.x - pj.x, ly = pl.y - pj.y, lz = pl.z - pj.z;
            float nx = iy * kz - iz * ky;
            float ny = iz * kx - ix * kz;
            float nz = ix * ky - iy * kx;
            float dot = fmaf(nx, lx, fmaf(ny, ly, nz * lz));
            float m1  = fmaf(nx, nx, fmaf(ny, ny, nz * nz));
            float m2  = fmaf(lx, lx, fmaf(ly, ly, lz * lz));
            float cosY = clip1(dot * rsqrtf(fmaxf(m1 * m2, 1e-24f)));
            float sinY = sqrtf(fmaxf(1.0f - cosY * cosY, 0.0f));
            e += K * fmaf(a2, fmaf(2.0f * sinY, sinY, -1.0f), fmaf(a1, sinY, a0));
        }
    }

    reduce_out(e, out);
}

// ---------------------------------------------------------------------------
// launch
// ---------------------------------------------------------------------------
static inline int blocks_for(int n_terms, int iters) {
    long long groups = ((long long)n_terms + 32LL * iters - 1) / (32LL * iters);
    return groups < 1 ? 1 : (int)groups;
}

extern "C" void kernel_launch(void* const* d_in, const int* in_sizes, int n_in,
                              void* d_out, int out_size) {
    const float* coords      = (const float*)d_in[0];
    const int*   bond_index  = (const int*)d_in[1];
    const float* bond_r0     = (const float*)d_in[2];
    const float* bond_k      = (const float*)d_in[3];
    const int*   angle_index = (const int*)d_in[4];
    const float* angle_k     = (const float*)d_in[5];
    const float* angle_c0    = (const float*)d_in[6];
    const float* angle_c1    = (const float*)d_in[7];
    const float* angle_c2    = (const float*)d_in[8];
    const int*   tor_index   = (const int*)d_in[9];
    const float* tor_k       = (const float*)d_in[10];
    const int*   tor_order   = (const int*)d_in[11];
    const float* tor_cos     = (const float*)d_in[12];
    const int*   inv_index   = (const int*)d_in[13];
    const float* inv_k       = (const float*)d_in[14];
    const float* inv_c0      = (const float*)d_in[15];
    const float* inv_c1      = (const float*)d_in[16];
    const float* inv_c2      = (const float*)d_in[17];
    const int*   nb_index    = (const int*)d_in[18];
    const float* vdw_min     = (const float*)d_in[19];
    const float* vdw_depth   = (const float*)d_in[20];
    const float* vdw_thr     = (const float*)d_in[21];
    float* out = (float*)d_out;

    const int NB = in_sizes[1]  / 2;
    const int NA = in_sizes[4]  / 3;
    const int NT = in_sizes[9]  / 4;
    const int NI = in_sizes[13] / 4;
    const int NC = in_sizes[18] / 2;
    const int natoms = in_sizes[0] / (3 * NBATCH);  // B fixed = 8
    const int total  = NBATCH * natoms;

    const int T = 256;
    pack_kernel<<<(total + T - 1) / T, T>>>(coords, out, natoms);

    const int cB = blocks_for(NC, 8);
    const int tB = blocks_for(NT, 4);
    const int aB = blocks_for(NA, 4);
    const int bB = blocks_for(NB, 2);
    const int iB = blocks_for(NI, 2);
    const int grid = cB + tB + aB + bB + iB;

    fused_kernel<<<grid, T>>>(
        coords,
        (const int2*)nb_index, vdw_min, vdw_depth, vdw_thr, NC, cB,
        (const int4*)tor_index, tor_k, tor_order, tor_cos, NT, tB,
        angle_index, angle_k, angle_c0, angle_c1, angle_c2, NA, aB,
        (const int2*)bond_index, bond_r0, bond_k, NB, bB,
        (const int4*)inv_index, inv_k, inv_c0, inv_c1, inv_c2, NI, iB,
        natoms, out);
}

// round 6
// speedup vs baseline: 3.7353x; 1.0922x over previous
#include <cuda_runtime.h>
#include <cuda_bf16.h>
#include <cuda_fp16.h>

// ---------------------------------------------------------------------------
// UFF energy -> out[8]. Coords batch-major fp16 half4 (uint2): one atom's 8
// batches = 64B = 2 L2 sectors, read as one coalesced transaction by the 8
// lanes handling that term's batches. This round: dual-chain interleaved
// iterations (hide the idx->coord dependent L2 hop), half2 difference math,
// and branch-free Chebyshev torsion.
// ---------------------------------------------------------------------------

#define NBATCH 8
#define MAX_ATOMS 50000

__device__ uint2 g_h[MAX_ATOMS * NBATCH];

__device__ __forceinline__ float clip1(float x) {
    return fminf(fmaxf(x, -0.999999f), 0.999999f);
}

__device__ __forceinline__ uint2 ldraw(int atom, int b) {
    return __ldg(&g_h[atom * NBATCH + b]);
}

// dx,dy,dz = (a - c) computed in half2, converted to float
__device__ __forceinline__ void hdiff(uint2 a, uint2 c,
                                      float& dx, float& dy, float& dz) {
    __half2 axy = *reinterpret_cast<__half2*>(&a.x);
    __half2 az  = *reinterpret_cast<__half2*>(&a.y);
    __half2 cxy = *reinterpret_cast<__half2*>(&c.x);
    __half2 cz  = *reinterpret_cast<__half2*>(&c.y);
    __half2 dxy = __hsub2(axy, cxy);
    __half2 dzz = __hsub2(az, cz);
    float2 f = __half22float2(dxy);
    dx = f.x; dy = f.y; dz = __low2float(dzz);
}

// ---------------------------------------------------------------------------
// pack coords (B,N,3) f32 -> batch-major half4; zero out[8]
// ---------------------------------------------------------------------------
__global__ void pack_kernel(const float* __restrict__ coords,
                            float* __restrict__ out, int natoms) {
    int i = blockIdx.x * blockDim.x + threadIdx.x;
    if (i < NBATCH) out[i] = 0.0f;
    if (i < natoms * NBATCH) {
        int atom = i >> 3;
        int b    = i & 7;
        size_t src = ((size_t)b * natoms + atom) * 3;
        __half2 hxy = __floats2half2_rn(coords[src], coords[src + 1]);
        __half2 hz  = __floats2half2_rn(coords[src + 2], 0.0f);
        uint2 u;
        u.x = *reinterpret_cast<unsigned*>(&hxy);
        u.y = *reinterpret_cast<unsigned*>(&hz);
        g_h[i] = u;
    }
}

// ---------------------------------------------------------------------------
// per-block reduction: thread holds energy for (term-group, batch = lane&7)
// ---------------------------------------------------------------------------
__device__ __forceinline__ void reduce_out(float e, float* __restrict__ out) {
    e += __shfl_down_sync(0xFFFFFFFFu, e, 16);
    e += __shfl_down_sync(0xFFFFFFFFu, e, 8);
    __shared__ float s[NBATCH];
    if (threadIdx.x < NBATCH) s[threadIdx.x] = 0.0f;
    __syncthreads();
    if ((threadIdx.x & 31) < NBATCH) atomicAdd(&s[threadIdx.x & 7], e);
    __syncthreads();
    if (threadIdx.x < NBATCH) atomicAdd(&out[threadIdx.x], s[threadIdx.x]);
}

// ---------------------------------------------------------------------------
// term bodies
// ---------------------------------------------------------------------------
__device__ __forceinline__ float vdw_body(
    int t, int b, const int2* __restrict__ cidx, const float* __restrict__ cR,
    const float* __restrict__ cD, const float* __restrict__ cT,
    const float* __restrict__ coords, int natoms)
{
    int2  p  = __ldg(&cidx[t]);
    float R  = __ldg(&cR[t]);
    float D  = __ldg(&cD[t]);
    float t2 = __ldg(&cT[t]);
    uint2 A = ldraw(p.x, b);
    uint2 C = ldraw(p.y, b);
    float dx, dy, dz;
    hdiff(A, C, dx, dy, dz);
    float d2 = fmaf(dx, dx, fmaf(dy, dy, dz * dz));
    if (d2 < 4.0f) {
        // rare near-collision: (R/r)^12 is fp16-sensitive; redo in fp32
        size_t sa = ((size_t)b * natoms + p.x) * 3;
        size_t sc = ((size_t)b * natoms + p.y) * 3;
        float fdx = __ldg(&coords[sa])     - __ldg(&coords[sc]);
        float fdy = __ldg(&coords[sa + 1]) - __ldg(&coords[sc + 1]);
        float fdz = __ldg(&coords[sa + 2]) - __ldg(&coords[sc + 2]);
        d2 = fmaf(fdx, fdx, fmaf(fdy, fdy, fdz * fdz));
    }
    float x2 = (R * R) * __frcp_rn(fmaxf(d2, 1e-12f));
    float x6 = x2 * x2 * x2;
    float ep = D * fmaf(x6, x6, -2.0f * x6);
    return (d2 <= t2) ? ep : 0.0f;
}

__device__ __forceinline__ float torsion_body(
    int t, int b, const int4* __restrict__ tidx, const float* __restrict__ tk,
    const int* __restrict__ tord, const float* __restrict__ tcos)
{
    int4  q   = __ldg(&tidx[t]);
    float V2  = 0.5f * __ldg(&tk[t]);
    int   ord = __ldg(&tord[t]);
    float ctm = __ldg(&tcos[t]);
    uint2 q1 = ldraw(q.x, b);
    uint2 q2 = ldraw(q.y, b);
    uint2 q3 = ldraw(q.z, b);
    uint2 q4 = ldraw(q.w, b);
    float b1x, b1y, b1z, b2x, b2y, b2z, b3x, b3y, b3z;
    hdiff(q2, q1, b1x, b1y, b1z);
    hdiff(q3, q2, b2x, b2y, b2z);
    hdiff(q4, q3, b3x, b3y, b3z);
    float n1x = b1y * b2z - b1z * b2y;
    float n1y = b1z * b2x - b1x * b2z;
    float n1z = b1x * b2y - b1y * b2x;
    float n2x = b2y * b3z - b2z * b3y;
    float n2y = b2z * b3x - b2x * b3z;
    float n2z = b2x * b3y - b2y * b3x;
    float dot = fmaf(n1x, n2x, fmaf(n1y, n2y, n1z * n2z));
    float m1  = fmaf(n1x, n1x, fmaf(n1y, n1y, n1z * n1z));
    float m2  = fmaf(n2x, n2x, fmaf(n2y, n2y, n2z * n2z));
    float c   = clip1(dot * rsqrtf(fmaxf(m1 * m2, 1e-24f)));
    // branch-free T_ord(c) = cos(ord*phi), ord in [1,6]
    float c2 = 2.0f * c;
    float T1 = c;
    float T2 = fmaf(c2, T1, -1.0f);
    float T3 = fmaf(c2, T2, -T1);
    float T4 = fmaf(c2, T3, -T2);
    float T5 = fmaf(c2, T4, -T3);
    float T6 = fmaf(c2, T5, -T4);
    float Tn = (ord <= 1) ? T1 : (ord == 2) ? T2 : (ord == 3) ? T3
             : (ord == 4) ? T4 : (ord == 5) ? T5 : T6;
    return V2 * (1.0f - ctm * Tn);
}

// ---------------------------------------------------------------------------
// fused term kernel: vdw | torsion | angle | bond | inversion by block range.
// 256 threads = 32 term-groups x 8 batches. vdW/torsion use dual-chain
// interleaving: two independent term bodies per loop iteration.
// ---------------------------------------------------------------------------
__global__ __launch_bounds__(256)
void fused_kernel(
    const float* __restrict__ coords,
    const int2* __restrict__ cidx, const float* __restrict__ cR,
    const float* __restrict__ cD,  const float* __restrict__ cT,
    int nc, int cBlocks,
    const int4* __restrict__ tidx, const float* __restrict__ tk,
    const int* __restrict__ tord,  const float* __restrict__ tcos,
    int nt, int tBlocks,
    const int* __restrict__ aidx,  const float* __restrict__ ak,
    const float* __restrict__ ac0, const float* __restrict__ ac1,
    const float* __restrict__ ac2, int na, int aBlocks,
    const int2* __restrict__ bidx, const float* __restrict__ br0,
    const float* __restrict__ bk,  int nb, int bBlocks,
    const int4* __restrict__ iidx, const float* __restrict__ ik,
    const float* __restrict__ ic0, const float* __restrict__ ic1,
    const float* __restrict__ ic2, int ni, int iBlocks,
    int natoms, float* __restrict__ out)
{
    const int blk = blockIdx.x;
    const int b   = threadIdx.x & 7;   // batch
    const int grp = threadIdx.x >> 3;  // term-group (0..31)
    float e = 0.0f;

    if (blk < cBlocks) {
        // ---------------- vdW LJ (dual-chain) ----------------
        const int stride = cBlocks * 32;
        int t = blk * 32 + grp;
        for (; t + stride < nc; t += 2 * stride) {
            float ea = vdw_body(t,          b, cidx, cR, cD, cT, coords, natoms);
            float eb = vdw_body(t + stride, b, cidx, cR, cD, cT, coords, natoms);
            e += ea + eb;
        }
        if (t < nc)
            e += vdw_body(t, b, cidx, cR, cD, cT, coords, natoms);
    } else if (blk < cBlocks + tBlocks) {
        // ---------------- torsion (dual-chain) ----------------
        const int stride = tBlocks * 32;
        int t = (blk - cBlocks) * 32 + grp;
        for (; t + stride < nt; t += 2 * stride) {
            float ea = torsion_body(t,          b, tidx, tk, tord, tcos);
            float eb = torsion_body(t + stride, b, tidx, tk, tord, tcos);
            e += ea + eb;
        }
        if (t < nt)
            e += torsion_body(t, b, tidx, tk, tord, tcos);
    } else if (blk < cBlocks + tBlocks + aBlocks) {
        // ---------------- angle ----------------
        const int base = cBlocks + tBlocks, stride = aBlocks * 32;
        for (int t = (blk - base) * 32 + grp; t < na; t += stride) {
            int i0 = __ldg(&aidx[3 * t + 0]);
            int i1 = __ldg(&aidx[3 * t + 1]);
            int i2 = __ldg(&aidx[3 * t + 2]);
            float K  = __ldg(&ak[t]);
            float a0 = __ldg(&ac0[t]);
            float a1 = __ldg(&ac1[t]);
            float a2 = __ldg(&ac2[t]);
            uint2 p1 = ldraw(i0, b);
            uint2 p2 = ldraw(i1, b);
            uint2 p3 = ldraw(i2, b);
            float v1x, v1y, v1z, v2x, v2y, v2z;
            hdiff(p1, p2, v1x, v1y, v1z);
            hdiff(p3, p2, v2x, v2y, v2z);
            float dot = fmaf(v1x, v2x, fmaf(v1y, v2y, v1z * v2z));
            float n1  = fmaf(v1x, v1x, fmaf(v1y, v1y, v1z * v1z));
            float n2  = fmaf(v2x, v2x, fmaf(v2y, v2y, v2z * v2z));
            float ct  = clip1(dot * rsqrtf(fmaxf(n1 * n2, 1e-24f)));
            float cs  = ct * ct;
            float ss  = fmaxf(1.0f - cs, 1e-12f);
            e += K * fmaf(a2, cs - ss, fmaf(a1, ct, a0));
        }
    } else if (blk < cBlocks + tBlocks + aBlocks + bBlocks) {
        // ---------------- bond ----------------
        const int base = cBlocks + tBlocks + aBlocks, stride = bBlocks * 32;
        for (int t = (blk - base) * 32 + grp; t < nb; t += stride) {
            int2  p  = __ldg(&bidx[t]);
            float r0 = __ldg(&br0[t]);
            float k2 = 0.5f * __ldg(&bk[t]);
            uint2 A = ldraw(p.x, b);
            uint2 C = ldraw(p.y, b);
            float dx, dy, dz;
            hdiff(A, C, dx, dy, dz);
            float dist = sqrtf(fmaf(dx, dx, fmaf(dy, dy, dz * dz)));
            float dd = dist - r0;
            e += k2 * dd * dd;
        }
    } else {
        // ---------------- inversion ----------------
        const int base = cBlocks + tBlocks + aBlocks + bBlocks, stride = iBlocks * 32;
        for (int t = (blk - base) * 32 + grp; t < ni; t += stride) {
            int4  q  = __ldg(&iidx[t]);
            float K  = __ldg(&ik[t]);
            float a0 = __ldg(&ic0[t]);
            float a1 = __ldg(&ic1[t]);
            float a2 = __ldg(&ic2[t]);
            uint2 pi = ldraw(q.x, b);
            uint2 pj = ldraw(q.y, b);  // central
            uint2 pk = ldraw(q.z, b);
            uint2 pl = ldraw(q.w, b);
            float ix, iy, iz, kx, ky, kz, lx, ly, lz;
            hdiff(pi, pj, ix, iy, iz);
            hdiff(pk, pj, kx, ky, kz);
            hdiff(pl, pj, lx, ly, lz);
            float nx = iy * kz - iz * ky;
            float ny = iz * kx - ix * kz;
            float nz = ix * ky - iy * kx;
            float dot = fmaf(nx, lx, fmaf(ny, ly, nz * lz));
            float m1  = fmaf(nx, nx, fmaf(ny, ny, nz * nz));
            float m2  = fmaf(lx, lx, fmaf(ly, ly, lz * lz));
            float cosY = clip1(dot * rsqrtf(fmaxf(m1 * m2, 1e-24f)));
            float sinY = sqrtf(fmaxf(1.0f - cosY * cosY, 0.0f));
            e += K * fmaf(a2, fmaf(2.0f * sinY, sinY, -1.0f), fmaf(a1, sinY, a0));
        }
    }

    reduce_out(e, out);
}

// ---------------------------------------------------------------------------
// launch
// ---------------------------------------------------------------------------
static inline int blocks_for(int n_terms, int iters) {
    long long groups = ((long long)n_terms + 32LL * iters - 1) / (32LL * iters);
    return groups < 1 ? 1 : (int)groups;
}

extern "C" void kernel_launch(void* const* d_in, const int* in_sizes, int n_in,
                              void* d_out, int out_size) {
    const float* coords      = (const float*)d_in[0];
    const int*   bond_index  = (const int*)d_in[1];
    const float* bond_r0     = (const float*)d_in[2];
    const float* bond_k      = (const float*)d_in[3];
    const int*   angle_index = (const int*)d_in[4];
    const float* angle_k     = (const float*)d_in[5];
    const float* angle_c0    = (const float*)d_in[6];
    const float* angle_c1    = (const float*)d_in[7];
    const float* angle_c2    = (const float*)d_in[8];
    const int*   tor_index   = (const int*)d_in[9];
    const float* tor_k       = (const float*)d_in[10];
    const int*   tor_order   = (const int*)d_in[11];
    const float* tor_cos     = (const float*)d_in[12];
    const int*   inv_index   = (const int*)d_in[13];
    const float* inv_k       = (const float*)d_in[14];
    const float* inv_c0      = (const float*)d_in[15];
    const float* inv_c1      = (const float*)d_in[16];
    const float* inv_c2      = (const float*)d_in[17];
    const int*   nb_index    = (const int*)d_in[18];
    const float* vdw_min     = (const float*)d_in[19];
    const float* vdw_depth   = (const float*)d_in[20];
    const float* vdw_thr     = (const float*)d_in[21];
    float* out = (float*)d_out;

    const int NB = in_sizes[1]  / 2;
    const int NA = in_sizes[4]  / 3;
    const int NT = in_sizes[9]  / 4;
    const int NI = in_sizes[13] / 4;
    const int NC = in_sizes[18] / 2;
    const int natoms = in_sizes[0] / (3 * NBATCH);  // B fixed = 8
    const int total  = NBATCH * natoms;

    const int T = 256;
    pack_kernel<<<(total + T - 1) / T, T>>>(coords, out, natoms);

    const int cB = blocks_for(NC, 8);
    const int tB = blocks_for(NT, 4);
    const int aB = blocks_for(NA, 4);
    const int bB = blocks_for(NB, 2);
    const int iB = blocks_for(NI, 2);
    const int grid = cB + tB + aB + bB + iB;

    fused_kernel<<<grid, T>>>(
        coords,
        (const int2*)nb_index, vdw_min, vdw_depth, vdw_thr, NC, cB,
        (const int4*)tor_index, tor_k, tor_order, tor_cos, NT, tB,
        angle_index, angle_k, angle_c0, angle_c1, angle_c2, NA, aB,
        (const int2*)bond_index, bond_r0, bond_k, NB, bB,
        (const int4*)inv_index, inv_k, inv_c0, inv_c1, inv_c2, NI, iB,
        natoms, out);
}

// round 8
// speedup vs baseline: 4.1369x; 1.1075x over previous
#include <cuda_runtime.h>
#include <cuda_bf16.h>
#include <cuda_fp16.h>

// ---------------------------------------------------------------------------
// UFF energy -> out[8]. Coords batch-major fp16 half4: g_h[atom*8+b].
// This round: 4 lanes x 2 batches per term (uint4 coord loads = 2 batches
// per load), so one warp covers 8 terms -> load-side warp instructions per
// term halve; the 2 batch evals per thread are independent math chains.
// ---------------------------------------------------------------------------

#define NBATCH 8
#define MAX_ATOMS 50000

__device__ uint2 g_h[MAX_ATOMS * NBATCH];   // [atom][batch] half4 (8B)

__device__ __forceinline__ float clip1(float x) {
    return fminf(fmaxf(x, -0.999999f), 0.999999f);
}

__device__ __forceinline__ __half2 u2h(unsigned u) {
    return *reinterpret_cast<__half2*>(&u);
}

// load both batches (2*bp, 2*bp+1) of one atom: 16B
__device__ __forceinline__ uint4 ldco2(int atom, int bp) {
    const uint4* g4 = reinterpret_cast<const uint4*>(g_h);
    return __ldg(&g4[atom * 4 + bp]);
}

// d0,d1 = per-batch (a - c) differences, computed in half2 then widened
__device__ __forceinline__ void hdiff2(uint4 a, uint4 c, float3& d0, float3& d1) {
    __half2 dxy0 = __hsub2(u2h(a.x), u2h(c.x));
    __half2 dz0  = __hsub2(u2h(a.y), u2h(c.y));
    __half2 dxy1 = __hsub2(u2h(a.z), u2h(c.z));
    __half2 dz1  = __hsub2(u2h(a.w), u2h(c.w));
    float2 f0 = __half22float2(dxy0);
    float2 f1 = __half22float2(dxy1);
    d0 = make_float3(f0.x, f0.y, __low2float(dz0));
    d1 = make_float3(f1.x, f1.y, __low2float(dz1));
}

// ---------------------------------------------------------------------------
// pack coords (B,N,3) f32 -> batch-major half4; zero out[8]
// ---------------------------------------------------------------------------
__global__ void pack_kernel(const float* __restrict__ coords,
                            float* __restrict__ out, int natoms) {
    int i = blockIdx.x * blockDim.x + threadIdx.x;
    if (i < NBATCH) out[i] = 0.0f;
    if (i < natoms * NBATCH) {
        int atom = i >> 3;
        int b    = i & 7;
        size_t src = ((size_t)b * natoms + atom) * 3;
        __half2 hxy = __floats2half2_rn(coords[src], coords[src + 1]);
        __half2 hz  = __floats2half2_rn(coords[src + 2], 0.0f);
        uint2 u;
        u.x = *reinterpret_cast<unsigned*>(&hxy);
        u.y = *reinterpret_cast<unsigned*>(&hz);
        g_h[i] = u;
    }
}

// ---------------------------------------------------------------------------
// reduction: thread holds e0 (batch 2*bp) and e1 (batch 2*bp+1), bp = lane&3
// ---------------------------------------------------------------------------
__device__ __forceinline__ void reduce_out2(float e0, float e1,
                                            float* __restrict__ out) {
    #pragma unroll
    for (int off = 16; off >= 4; off >>= 1) {
        e0 += __shfl_down_sync(0xFFFFFFFFu, e0, off);
        e1 += __shfl_down_sync(0xFFFFFFFFu, e1, off);
    }
    __shared__ float s[NBATCH];
    if (threadIdx.x < NBATCH) s[threadIdx.x] = 0.0f;
    __syncthreads();
    if ((threadIdx.x & 31) < 4) {
        int bp = threadIdx.x & 3;
        atomicAdd(&s[2 * bp],     e0);
        atomicAdd(&s[2 * bp + 1], e1);
    }
    __syncthreads();
    if (threadIdx.x < NBATCH) atomicAdd(&out[threadIdx.x], s[threadIdx.x]);
}

// ---------------------------------------------------------------------------
// fp32 fallback distance^2 for near-collision vdW pairs
// ---------------------------------------------------------------------------
__device__ __forceinline__ float d2_fp32(const float* __restrict__ coords,
                                         int natoms, int b, int2 p) {
    size_t sa = ((size_t)b * natoms + p.x) * 3;
    size_t sc = ((size_t)b * natoms + p.y) * 3;
    float dx = __ldg(&coords[sa])     - __ldg(&coords[sc]);
    float dy = __ldg(&coords[sa + 1]) - __ldg(&coords[sc + 1]);
    float dz = __ldg(&coords[sa + 2]) - __ldg(&coords[sc + 2]);
    return fmaf(dx, dx, fmaf(dy, dy, dz * dz));
}

__device__ __forceinline__ float lj(float d2, float R2, float D, float t2) {
    float x2 = R2 * __fdividef(1.0f, fmaxf(d2, 1e-12f));
    float x6 = x2 * x2 * x2;
    float ep = D * fmaf(x6, x6, -2.0f * x6);
    return (d2 <= t2) ? ep : 0.0f;
}

// ---------------------------------------------------------------------------
// term bodies (each evaluates batches 2*bp and 2*bp+1)
// ---------------------------------------------------------------------------
__device__ __forceinline__ void vdw_body(
    int t, int bp, const int2* __restrict__ cidx, const float* __restrict__ cR,
    const float* __restrict__ cD, const float* __restrict__ cT,
    const float* __restrict__ coords, int natoms, float& e0, float& e1)
{
    int2  p  = __ldg(&cidx[t]);
    float R  = __ldg(&cR[t]);
    float D  = __ldg(&cD[t]);
    float t2 = __ldg(&cT[t]);
    uint4 A = ldco2(p.x, bp);
    uint4 C = ldco2(p.y, bp);
    float3 d0, d1;
    hdiff2(A, C, d0, d1);
    float d20 = fmaf(d0.x, d0.x, fmaf(d0.y, d0.y, d0.z * d0.z));
    float d21 = fmaf(d1.x, d1.x, fmaf(d1.y, d1.y, d1.z * d1.z));
    if (d20 < 4.0f) d20 = d2_fp32(coords, natoms, 2 * bp,     p);
    if (d21 < 4.0f) d21 = d2_fp32(coords, natoms, 2 * bp + 1, p);
    float R2 = R * R;
    e0 += lj(d20, R2, D, t2);
    e1 += lj(d21, R2, D, t2);
}

__device__ __forceinline__ float tor_e(float3 b1, float3 b2, float3 b3,
                                       float V2, int ord, float ctm) {
    float n1x = b1.y * b2.z - b1.z * b2.y;
    float n1y = b1.z * b2.x - b1.x * b2.z;
    float n1z = b1.x * b2.y - b1.y * b2.x;
    float n2x = b2.y * b3.z - b2.z * b3.y;
    float n2y = b2.z * b3.x - b2.x * b3.z;
    float n2z = b2.x * b3.y - b2.y * b3.x;
    float dot = fmaf(n1x, n2x, fmaf(n1y, n2y, n1z * n2z));
    float m1  = fmaf(n1x, n1x, fmaf(n1y, n1y, n1z * n1z));
    float m2  = fmaf(n2x, n2x, fmaf(n2y, n2y, n2z * n2z));
    float c   = clip1(dot * rsqrtf(fmaxf(m1 * m2, 1e-24f)));
    float c2 = 2.0f * c;
    float T1 = c;
    float T2 = fmaf(c2, T1, -1.0f);
    float T3 = fmaf(c2, T2, -T1);
    float T4 = fmaf(c2, T3, -T2);
    float T5 = fmaf(c2, T4, -T3);
    float T6 = fmaf(c2, T5, -T4);
    float Tn = (ord <= 1) ? T1 : (ord == 2) ? T2 : (ord == 3) ? T3
             : (ord == 4) ? T4 : (ord == 5) ? T5 : T6;
    return V2 * (1.0f - ctm * Tn);
}

__device__ __forceinline__ void torsion_body(
    int t, int bp, const int4* __restrict__ tidx, const float* __restrict__ tk,
    const int* __restrict__ tord, const float* __restrict__ tcos,
    float& e0, float& e1)
{
    int4  q   = __ldg(&tidx[t]);
    float V2  = 0.5f * __ldg(&tk[t]);
    int   ord = __ldg(&tord[t]);
    float ctm = __ldg(&tcos[t]);
    uint4 q1 = ldco2(q.x, bp);
    uint4 q2 = ldco2(q.y, bp);
    uint4 q3 = ldco2(q.z, bp);
    uint4 q4 = ldco2(q.w, bp);
    float3 b1a, b1b, b2a, b2b, b3a, b3b;
    hdiff2(q2, q1, b1a, b1b);
    hdiff2(q3, q2, b2a, b2b);
    hdiff2(q4, q3, b3a, b3b);
    e0 += tor_e(b1a, b2a, b3a, V2, ord, ctm);
    e1 += tor_e(b1b, b2b, b3b, V2, ord, ctm);
}

// ---------------------------------------------------------------------------
// fused term kernel: vdw | torsion | angle | bond | inversion by block range.
// 256 threads = 64 term-groups x 4 lanes x 2 batches.
// ---------------------------------------------------------------------------
__global__ __launch_bounds__(256)
void fused_kernel(
    const float* __restrict__ coords,
    const int2* __restrict__ cidx, const float* __restrict__ cR,
    const float* __restrict__ cD,  const float* __restrict__ cT,
    int nc, int cBlocks,
    const int4* __restrict__ tidx, const float* __restrict__ tk,
    const int* __restrict__ tord,  const float* __restrict__ tcos,
    int nt, int tBlocks,
    const int* __restrict__ aidx,  const float* __restrict__ ak,
    const float* __restrict__ ac0, const float* __restrict__ ac1,
    const float* __restrict__ ac2, int na, int aBlocks,
    const int2* __restrict__ bidx, const float* __restrict__ br0,
    const float* __restrict__ bk,  int nb, int bBlocks,
    const int4* __restrict__ iidx, const float* __restrict__ ik,
    const float* __restrict__ ic0, const float* __restrict__ ic1,
    const float* __restrict__ ic2, int ni, int iBlocks,
    int natoms, float* __restrict__ out)
{
    const int blk = blockIdx.x;
    const int bp  = threadIdx.x & 3;   // batch pair (batches 2bp, 2bp+1)
    const int grp = threadIdx.x >> 2;  // term-group (0..63)
    float e0 = 0.0f, e1 = 0.0f;

    if (blk < cBlocks) {
        // ---------------- vdW LJ (dual-chain) ----------------
        const int stride = cBlocks * 64;
        int t = blk * 64 + grp;
        for (; t + stride < nc; t += 2 * stride) {
            vdw_body(t,          bp, cidx, cR, cD, cT, coords, natoms, e0, e1);
            vdw_body(t + stride, bp, cidx, cR, cD, cT, coords, natoms, e0, e1);
        }
        if (t < nc)
            vdw_body(t, bp, cidx, cR, cD, cT, coords, natoms, e0, e1);
    } else if (blk < cBlocks + tBlocks) {
        // ---------------- torsion ----------------
        const int stride = tBlocks * 64;
        for (int t = (blk - cBlocks) * 64 + grp; t < nt; t += stride)
            torsion_body(t, bp, tidx, tk, tord, tcos, e0, e1);
    } else if (blk < cBlocks + tBlocks + aBlocks) {
        // ---------------- angle ----------------
        const int base = cBlocks + tBlocks, stride = aBlocks * 64;
        for (int t = (blk - base) * 64 + grp; t < na; t += stride) {
            int i0 = __ldg(&aidx[3 * t + 0]);
            int i1 = __ldg(&aidx[3 * t + 1]);
            int i2 = __ldg(&aidx[3 * t + 2]);
            float K  = __ldg(&ak[t]);
            float a0 = __ldg(&ac0[t]);
            float a1 = __ldg(&ac1[t]);
            float a2 = __ldg(&ac2[t]);
            uint4 p1 = ldco2(i0, bp);
            uint4 p2 = ldco2(i1, bp);
            uint4 p3 = ldco2(i2, bp);
            float3 v1a, v1b, v2a, v2b;
            hdiff2(p1, p2, v1a, v1b);
            hdiff2(p3, p2, v2a, v2b);
            #pragma unroll
            for (int s = 0; s < 2; s++) {
                float3 v1 = s ? v1b : v1a;
                float3 v2 = s ? v2b : v2a;
                float dot = fmaf(v1.x, v2.x, fmaf(v1.y, v2.y, v1.z * v2.z));
                float n1  = fmaf(v1.x, v1.x, fmaf(v1.y, v1.y, v1.z * v1.z));
                float n2  = fmaf(v2.x, v2.x, fmaf(v2.y, v2.y, v2.z * v2.z));
                float ct  = clip1(dot * rsqrtf(fmaxf(n1 * n2, 1e-24f)));
                float cs  = ct * ct;
                float ss  = fmaxf(1.0f - cs, 1e-12f);
                float ee  = K * fmaf(a2, cs - ss, fmaf(a1, ct, a0));
                if (s) e1 += ee; else e0 += ee;
            }
        }
    } else if (blk < cBlocks + tBlocks + aBlocks + bBlocks) {
        // ---------------- bond ----------------
        const int base = cBlocks + tBlocks + aBlocks, stride = bBlocks * 64;
        for (int t = (blk - base) * 64 + grp; t < nb; t += stride) {
            int2  p  = __ldg(&bidx[t]);
            float r0 = __ldg(&br0[t]);
            float k2 = 0.5f * __ldg(&bk[t]);
            uint4 A = ldco2(p.x, bp);
            uint4 C = ldco2(p.y, bp);
            float3 d0, d1;
            hdiff2(A, C, d0, d1);
            float s0 = fmaxf(fmaf(d0.x, d0.x, fmaf(d0.y, d0.y, d0.z * d0.z)), 1e-24f);
            float s1 = fmaxf(fmaf(d1.x, d1.x, fmaf(d1.y, d1.y, d1.z * d1.z)), 1e-24f);
            float dd0 = s0 * rsqrtf(s0) - r0;   // sqrt(s0) - r0
            float dd1 = s1 * rsqrtf(s1) - r0;
            e0 += k2 * dd0 * dd0;
            e1 += k2 * dd1 * dd1;
        }
    } else {
        // ---------------- inversion ----------------
        const int base = cBlocks + tBlocks + aBlocks + bBlocks, stride = iBlocks * 64;
        for (int t = (blk - base) * 64 + grp; t < ni; t += stride) {
            int4  q  = __ldg(&iidx[t]);
            float K  = __ldg(&ik[t]);
            float a0 = __ldg(&ic0[t]);
            float a1 = __ldg(&ic1[t]);
            float a2 = __ldg(&ic2[t]);
            uint4 pi = ldco2(q.x, bp);
            uint4 pj = ldco2(q.y, bp);  // central
            uint4 pk = ldco2(q.z, bp);
            uint4 pl = ldco2(q.w, bp);
            float3 ia, ib, ka, kb, la, lb;
            hdiff2(pi, pj, ia, ib);
            hdiff2(pk, pj, ka, kb);
            hdiff2(pl, pj, la, lb);
            #pragma unroll
            for (int s = 0; s < 2; s++) {
                float3 vi = s ? ib : ia;
                float3 vk = s ? kb : ka;
                float3 vl = s ? lb : la;
                float nx = vi.y * vk.z - vi.z * vk.y;
                float ny = vi.z * vk.x - vi.x * vk.z;
                float nz = vi.x * vk.y - vi.y * vk.x;
                float dot = fmaf(nx, vl.x, fmaf(ny, vl.y, nz * vl.z));
                float m1  = fmaf(nx, nx, fmaf(ny, ny, nz * nz));
                float m2  = fmaf(vl.x, vl.x, fmaf(vl.y, vl.y, vl.z * vl.z));
                float cosY = clip1(dot * rsqrtf(fmaxf(m1 * m2, 1e-24f)));
                float s2 = fmaxf(1.0f - cosY * cosY, 1e-24f);
                float sinY = s2 * rsqrtf(s2);  // sqrt
                float ee = K * fmaf(a2, fmaf(2.0f * sinY, sinY, -1.0f), fmaf(a1, sinY, a0));
                if (s) e1 += ee; else e0 += ee;
            }
        }
    }

    reduce_out2(e0, e1, out);
}

// ---------------------------------------------------------------------------
// launch
// ---------------------------------------------------------------------------
static inline int blocks_for(int n_terms, int iters) {
    long long groups = ((long long)n_terms + 64LL * iters - 1) / (64LL * iters);
    return groups < 1 ? 1 : (int)groups;
}

extern "C" void kernel_launch(void* const* d_in, const int* in_sizes, int n_in,
                              void* d_out, int out_size) {
    const float* coords      = (const float*)d_in[0];
    const int*   bond_index  = (const int*)d_in[1];
    const float* bond_r0     = (const float*)d_in[2];
    const float* bond_k      = (const float*)d_in[3];
    const int*   angle_index = (const int*)d_in[4];
    const float* angle_k     = (const float*)d_in[5];
    const float* angle_c0    = (const float*)d_in[6];
    const float* angle_c1    = (const float*)d_in[7];
    const float* angle_c2    = (const float*)d_in[8];
    const int*   tor_index   = (const int*)d_in[9];
    const float* tor_k       = (const float*)d_in[10];
    const int*   tor_order   = (const int*)d_in[11];
    const float* tor_cos     = (const float*)d_in[12];
    const int*   inv_index   = (const int*)d_in[13];
    const float* inv_k       = (const float*)d_in[14];
    const float* inv_c0      = (const float*)d_in[15];
    const float* inv_c1      = (const float*)d_in[16];
    const float* inv_c2      = (const float*)d_in[17];
    const int*   nb_index    = (const int*)d_in[18];
    const float* vdw_min     = (const float*)d_in[19];
    const float* vdw_depth   = (const float*)d_in[20];
    const float* vdw_thr     = (const float*)d_in[21];
    float* out = (float*)d_out;

    const int NB = in_sizes[1]  / 2;
    const int NA = in_sizes[4]  / 3;
    const int NT = in_sizes[9]  / 4;
    const int NI = in_sizes[13] / 4;
    const int NC = in_sizes[18] / 2;
    const int natoms = in_sizes[0] / (3 * NBATCH);  // B fixed = 8
    const int total  = NBATCH * natoms;

    const int T = 256;
    pack_kernel<<<(total + T - 1) / T, T>>>(coords, out, natoms);

    const int cB = blocks_for(NC, 4);
    const int tB = blocks_for(NT, 2);
    const int aB = blocks_for(NA, 2);
    const int bB = blocks_for(NB, 1);
    const int iB = blocks_for(NI, 1);
    const int grid = cB + tB + aB + bB + iB;

    fused_kernel<<<grid, T>>>(
        coords,
        (const int2*)nb_index, vdw_min, vdw_depth, vdw_thr, NC, cB,
        (const int4*)tor_index, tor_k, tor_order, tor_cos, NT, tB,
        angle_index, angle_k, angle_c0, angle_c1, angle_c2, NA, aB,
        (const int2*)bond_index, bond_r0, bond_k, NB, bB,
        (const int4*)inv_index, inv_k, inv_c0, inv_c1, inv_c2, NI, iB,
        natoms, out);
}